// round 1
// baseline (speedup 1.0000x reference)
#include <cuda_runtime.h>

#define EMBED 1024
#define FFN_DIM 4096
#define VEC4 (EMBED / 4)   // 256 float4 per row
#define EPS 1e-5f

// Scratch (no allocations allowed)
__device__ __align__(16) float d_h[FFN_DIM];
__device__ __align__(16) float d_a[EMBED];
__device__ __align__(16) float d_f[EMBED];
__device__ float d_cvec[4];

__device__ __forceinline__ void circuit4(const float* __restrict__ p, float* out) {
    float c0 = cosf(p[0]), c1 = cosf(p[1]), c2 = cosf(p[2]), c3 = cosf(p[3]);
    out[0] = c1 * c2 * c3;
    out[1] = c0 * c1;
    out[2] = c0 * c1 * c2;
    out[3] = c0 * c1 * c2 * c3;
}

// Kernel A: h = relu(w2 @ cvec_f)  (FFN_DIM elements), plus stash attn cvec.
__global__ void kA(const float* __restrict__ attn_p,
                   const float* __restrict__ ffn_p,
                   const float* __restrict__ w2) {
    float cf[4];
    circuit4(ffn_p, cf);
    int k = blockIdx.x * blockDim.x + threadIdx.x;
    if (k < FFN_DIM) {
        float4 w = reinterpret_cast<const float4*>(w2)[k];  // w2 is [FFN,4] row-major
        float pre = w.x * cf[0] + w.y * cf[1] + w.z * cf[2] + w.w * cf[3];
        d_h[k] = fmaxf(pre, 0.0f);
    }
    if (blockIdx.x == 0 && threadIdx.x < 4) {
        float ca[4];
        circuit4(attn_p, ca);
        d_cvec[threadIdx.x] = ca[threadIdx.x];
    }
}

// Kernel B: per output element e, a[e] = w_mix[e,:] . tile(cvec), f[e] = w_out[e,:] . h
__global__ void __launch_bounds__(256) kB(const float* __restrict__ w_mix,
                                          const float* __restrict__ w_out) {
    const int e = blockIdx.x;
    const int t = threadIdx.x;
    const float c0 = d_cvec[0], c1 = d_cvec[1], c2 = d_cvec[2], c3 = d_cvec[3];

    // w_mix row: 256 float4, one per thread; pattern repeats every 4 elements
    float4 wm = reinterpret_cast<const float4*>(w_mix + (size_t)e * EMBED)[t];
    float sa = wm.x * c0 + wm.y * c1 + wm.z * c2 + wm.w * c3;

    // w_out row: 1024 float4, 4 per thread
    const float4* wo = reinterpret_cast<const float4*>(w_out + (size_t)e * FFN_DIM);
    const float4* h4 = reinterpret_cast<const float4*>(d_h);
    float sf = 0.0f;
#pragma unroll
    for (int i = 0; i < 4; i++) {
        float4 w = wo[t + i * 256];
        float4 h = h4[t + i * 256];
        sf += w.x * h.x + w.y * h.y + w.z * h.z + w.w * h.w;
    }

#pragma unroll
    for (int o = 16; o > 0; o >>= 1) {
        sa += __shfl_down_sync(0xffffffffu, sa, o);
        sf += __shfl_down_sync(0xffffffffu, sf, o);
    }
    __shared__ float sh[16];
    int wid = t >> 5, lane = t & 31;
    if (lane == 0) { sh[wid] = sa; sh[8 + wid] = sf; }
    __syncthreads();
    if (t == 0) {
        float ta = 0.0f, tf = 0.0f;
#pragma unroll
        for (int i = 0; i < 8; i++) { ta += sh[i]; tf += sh[8 + i]; }
        d_a[e] = ta;
        d_f[e] = tf;
    }
}

// Main kernel: one block per token row; row lives in registers (1 float4/thread).
// out = LN2( LN1(x + a) + f )
__global__ void __launch_bounds__(256) kMain(const float4* __restrict__ x,
                                             const float4* __restrict__ g1,
                                             const float4* __restrict__ b1,
                                             const float4* __restrict__ g2,
                                             const float4* __restrict__ b2,
                                             float4* __restrict__ out) {
    const int row = blockIdx.x;
    const int t = threadIdx.x;
    const int wid = t >> 5, lane = t & 31;
    __shared__ float sh[18];

    const float4* a4 = reinterpret_cast<const float4*>(d_a);
    const float4* f4 = reinterpret_cast<const float4*>(d_f);

    float4 xv = x[(size_t)row * VEC4 + t];
    float4 av = a4[t];
    float4 tv;
    tv.x = xv.x + av.x; tv.y = xv.y + av.y; tv.z = xv.z + av.z; tv.w = xv.w + av.w;

    // --- reduction 1: mean/var of tv over the row ---
    float s = tv.x + tv.y + tv.z + tv.w;
    float q = tv.x * tv.x + tv.y * tv.y + tv.z * tv.z + tv.w * tv.w;
#pragma unroll
    for (int o = 16; o > 0; o >>= 1) {
        s += __shfl_down_sync(0xffffffffu, s, o);
        q += __shfl_down_sync(0xffffffffu, q, o);
    }
    if (lane == 0) { sh[wid] = s; sh[8 + wid] = q; }
    __syncthreads();
    if (t == 0) {
        float ts = 0.0f, tq = 0.0f;
#pragma unroll
        for (int i = 0; i < 8; i++) { ts += sh[i]; tq += sh[8 + i]; }
        float m = ts * (1.0f / EMBED);
        float v = tq * (1.0f / EMBED) - m * m;
        sh[16] = m;
        sh[17] = rsqrtf(v + EPS);
    }
    __syncthreads();
    float m1 = sh[16], r1 = sh[17];

    float4 g1v = g1[t], b1v = b1[t], fv = f4[t];
    float4 z;
    z.x = g1v.x * (tv.x - m1) * r1 + b1v.x + fv.x;
    z.y = g1v.y * (tv.y - m1) * r1 + b1v.y + fv.y;
    z.z = g1v.z * (tv.z - m1) * r1 + b1v.z + fv.z;
    z.w = g1v.w * (tv.w - m1) * r1 + b1v.w + fv.w;

    // --- reduction 2: mean/var of z ---
    s = z.x + z.y + z.z + z.w;
    q = z.x * z.x + z.y * z.y + z.z * z.z + z.w * z.w;
#pragma unroll
    for (int o = 16; o > 0; o >>= 1) {
        s += __shfl_down_sync(0xffffffffu, s, o);
        q += __shfl_down_sync(0xffffffffu, q, o);
    }
    if (lane == 0) { sh[wid] = s; sh[8 + wid] = q; }
    __syncthreads();
    if (t == 0) {
        float ts = 0.0f, tq = 0.0f;
#pragma unroll
        for (int i = 0; i < 8; i++) { ts += sh[i]; tq += sh[8 + i]; }
        float m = ts * (1.0f / EMBED);
        float v = tq * (1.0f / EMBED) - m * m;
        sh[16] = m;
        sh[17] = rsqrtf(v + EPS);
    }
    __syncthreads();
    float m2 = sh[16], r2 = sh[17];

    float4 g2v = g2[t], b2v = b2[t];
    float4 o;
    o.x = g2v.x * (z.x - m2) * r2 + b2v.x;
    o.y = g2v.y * (z.y - m2) * r2 + b2v.y;
    o.z = g2v.z * (z.z - m2) * r2 + b2v.z;
    o.w = g2v.w * (z.w - m2) * r2 + b2v.w;
    out[(size_t)row * VEC4 + t] = o;
}

extern "C" void kernel_launch(void* const* d_in, const int* in_sizes, int n_in,
                              void* d_out, int out_size) {
    // metadata order: x, wq, wk, wv, w_mix, attn_params, w1, w2, w_out,
    //                 ffn_params, ln1_g, ln1_b, ln2_g, ln2_b
    const float* x      = (const float*)d_in[0];
    const float* w_mix  = (const float*)d_in[4];
    const float* attn_p = (const float*)d_in[5];
    const float* w2     = (const float*)d_in[7];
    const float* w_out  = (const float*)d_in[8];
    const float* ffn_p  = (const float*)d_in[9];
    const float* ln1_g  = (const float*)d_in[10];
    const float* ln1_b  = (const float*)d_in[11];
    const float* ln2_g  = (const float*)d_in[12];
    const float* ln2_b  = (const float*)d_in[13];

    const int n_rows = in_sizes[0] / EMBED;  // B*S = 16384

    kA<<<FFN_DIM / 256, 256>>>(attn_p, ffn_p, w2);
    kB<<<EMBED, 256>>>(w_mix, w_out);
    kMain<<<n_rows, 256>>>(
        (const float4*)x,
        (const float4*)ln1_g, (const float4*)ln1_b,
        (const float4*)ln2_g, (const float4*)ln2_b,
        (float4*)d_out);
}

// round 2
// speedup vs baseline: 1.0447x; 1.0447x over previous
#include <cuda_runtime.h>

#define EMBED 1024
#define FFN_DIM 4096
#define VEC4 (EMBED / 4)   // 256 float4 per row
#define EPS 1e-5f

// Scratch (no allocations allowed)
__device__ __align__(16) float d_a[EMBED];
__device__ __align__(16) float d_f[EMBED];

__device__ __forceinline__ void circuit4(const float* __restrict__ p, float* out) {
    float c0 = cosf(p[0]), c1 = cosf(p[1]), c2 = cosf(p[2]), c3 = cosf(p[3]);
    out[0] = c1 * c2 * c3;
    out[1] = c0 * c1;
    out[2] = c0 * c1 * c2;
    out[3] = c0 * c1 * c2 * c3;
}

// Fused constant-vector kernel: per output element e,
//   a[e] = w_mix[e,:] . tile(cvec_attn)
//   f[e] = w_out[e,:] . relu(w2 @ cvec_ffn)
// Each block recomputes h = relu(w2 @ cvec_ffn) into smem (w2 is 64KB, L1/L2-hot).
__global__ void __launch_bounds__(256) kFuse(const float* __restrict__ w_mix,
                                             const float* __restrict__ w_out,
                                             const float* __restrict__ w2,
                                             const float* __restrict__ attn_p,
                                             const float* __restrict__ ffn_p) {
    const int e = blockIdx.x;
    const int t = threadIdx.x;
    __shared__ __align__(16) float h[FFN_DIM];

    float cf[4], ca[4];
    circuit4(ffn_p, cf);
    circuit4(attn_p, ca);

    // h[k] = relu(w2[k,:] . cf), 16 elements per thread, coalesced
#pragma unroll
    for (int i = 0; i < 16; i++) {
        int k = t + i * 256;
        float4 w = reinterpret_cast<const float4*>(w2)[k];
        h[k] = fmaxf(w.x * cf[0] + w.y * cf[1] + w.z * cf[2] + w.w * cf[3], 0.0f);
    }
    __syncthreads();

    // w_mix row: 256 float4, one per thread; attn pattern repeats every 4 elems
    float4 wm = reinterpret_cast<const float4*>(w_mix + (size_t)e * EMBED)[t];
    float sa = wm.x * ca[0] + wm.y * ca[1] + wm.z * ca[2] + wm.w * ca[3];

    // w_out row: 1024 float4, 4 per thread
    const float4* wo = reinterpret_cast<const float4*>(w_out + (size_t)e * FFN_DIM);
    const float4* h4 = reinterpret_cast<const float4*>(h);
    float sf = 0.0f;
#pragma unroll
    for (int i = 0; i < 4; i++) {
        float4 w = wo[t + i * 256];
        float4 hv = h4[t + i * 256];
        sf += w.x * hv.x + w.y * hv.y + w.z * hv.z + w.w * hv.w;
    }

#pragma unroll
    for (int o = 16; o > 0; o >>= 1) {
        sa += __shfl_down_sync(0xffffffffu, sa, o);
        sf += __shfl_down_sync(0xffffffffu, sf, o);
    }
    __shared__ float sh[16];
    int wid = t >> 5, lane = t & 31;
    if (lane == 0) { sh[wid] = sa; sh[8 + wid] = sf; }
    __syncthreads();
    if (t == 0) {
        float ta = 0.0f, tf = 0.0f;
#pragma unroll
        for (int i = 0; i < 8; i++) { ta += sh[i]; tf += sh[8 + i]; }
        d_a[e] = ta;
        d_f[e] = tf;
    }
}

// Main kernel: one WARP per token row, 8 float4 per lane, shfl-only reductions.
// out = LN2( LN1(x + a) + f )
__global__ void __launch_bounds__(256) kMain(const float4* __restrict__ x,
                                             const float4* __restrict__ g1,
                                             const float4* __restrict__ b1,
                                             const float4* __restrict__ g2,
                                             const float4* __restrict__ b2,
                                             float4* __restrict__ out) {
    const int warp = threadIdx.x >> 5;
    const int lane = threadIdx.x & 31;
    const size_t row = (size_t)blockIdx.x * 8 + warp;

    const float4* __restrict__ a4 = reinterpret_cast<const float4*>(d_a);
    const float4* __restrict__ f4 = reinterpret_cast<const float4*>(d_f);
    const float4* __restrict__ xr = x + row * VEC4;

    // Load row + attn constant: tv = x + a (front-batched, MLP=8)
    float4 tv[8];
#pragma unroll
    for (int i = 0; i < 8; i++) {
        float4 xv = xr[lane + 32 * i];
        float4 av = a4[lane + 32 * i];
        tv[i].x = xv.x + av.x; tv[i].y = xv.y + av.y;
        tv[i].z = xv.z + av.z; tv[i].w = xv.w + av.w;
    }

    // Reduction 1 (warp-only)
    float s = 0.0f, q = 0.0f;
#pragma unroll
    for (int i = 0; i < 8; i++) {
        s += tv[i].x + tv[i].y + tv[i].z + tv[i].w;
        q += tv[i].x * tv[i].x + tv[i].y * tv[i].y
           + tv[i].z * tv[i].z + tv[i].w * tv[i].w;
    }
#pragma unroll
    for (int o = 16; o > 0; o >>= 1) {
        s += __shfl_xor_sync(0xffffffffu, s, o);
        q += __shfl_xor_sync(0xffffffffu, q, o);
    }
    float m1 = s * (1.0f / EMBED);
    float r1 = rsqrtf(q * (1.0f / EMBED) - m1 * m1 + EPS);

    // z = g1*(tv-m1)*r1 + b1 + f  (in place), accumulate reduction 2
    s = 0.0f; q = 0.0f;
#pragma unroll
    for (int i = 0; i < 8; i++) {
        float4 gv = g1[lane + 32 * i];
        float4 bv = b1[lane + 32 * i];
        float4 fv = f4[lane + 32 * i];
        tv[i].x = gv.x * (tv[i].x - m1) * r1 + bv.x + fv.x;
        tv[i].y = gv.y * (tv[i].y - m1) * r1 + bv.y + fv.y;
        tv[i].z = gv.z * (tv[i].z - m1) * r1 + bv.z + fv.z;
        tv[i].w = gv.w * (tv[i].w - m1) * r1 + bv.w + fv.w;
        s += tv[i].x + tv[i].y + tv[i].z + tv[i].w;
        q += tv[i].x * tv[i].x + tv[i].y * tv[i].y
           + tv[i].z * tv[i].z + tv[i].w * tv[i].w;
    }
#pragma unroll
    for (int o = 16; o > 0; o >>= 1) {
        s += __shfl_xor_sync(0xffffffffu, s, o);
        q += __shfl_xor_sync(0xffffffffu, q, o);
    }
    float m2 = s * (1.0f / EMBED);
    float r2 = rsqrtf(q * (1.0f / EMBED) - m2 * m2 + EPS);

    float4* __restrict__ orow = out + row * VEC4;
#pragma unroll
    for (int i = 0; i < 8; i++) {
        float4 gv = g2[lane + 32 * i];
        float4 bv = b2[lane + 32 * i];
        float4 o;
        o.x = gv.x * (tv[i].x - m2) * r2 + bv.x;
        o.y = gv.y * (tv[i].y - m2) * r2 + bv.y;
        o.z = gv.z * (tv[i].z - m2) * r2 + bv.z;
        o.w = gv.w * (tv[i].w - m2) * r2 + bv.w;
        orow[lane + 32 * i] = o;
    }
}

extern "C" void kernel_launch(void* const* d_in, const int* in_sizes, int n_in,
                              void* d_out, int out_size) {
    // metadata order: x, wq, wk, wv, w_mix, attn_params, w1, w2, w_out,
    //                 ffn_params, ln1_g, ln1_b, ln2_g, ln2_b
    const float* x      = (const float*)d_in[0];
    const float* w_mix  = (const float*)d_in[4];
    const float* attn_p = (const float*)d_in[5];
    const float* w2     = (const float*)d_in[7];
    const float* w_out  = (const float*)d_in[8];
    const float* ffn_p  = (const float*)d_in[9];
    const float* ln1_g  = (const float*)d_in[10];
    const float* ln1_b  = (const float*)d_in[11];
    const float* ln2_g  = (const float*)d_in[12];
    const float* ln2_b  = (const float*)d_in[13];

    const int n_rows = in_sizes[0] / EMBED;  // B*S = 16384

    kFuse<<<EMBED, 256>>>(w_mix, w_out, w2, attn_p, ffn_p);
    kMain<<<n_rows / 8, 256>>>(
        (const float4*)x,
        (const float4*)ln1_g, (const float4*)ln1_b,
        (const float4*)ln2_g, (const float4*)ln2_b,
        (float4*)d_out);
}

// round 3
// speedup vs baseline: 1.3342x; 1.2772x over previous
#include <cuda_runtime.h>

#define EMBED 1024
#define FFN_DIM 4096
#define VEC4 (EMBED / 4)   // 256 float4 per row
#define EPS 1e-5f

// Scratch (no allocations allowed)
__device__ __align__(16) float d_a[EMBED];     // attn constant vector
__device__ __align__(16) float d_b1f[EMBED];   // ln1_b + ffn constant vector

__device__ __forceinline__ void circuit4(const float* __restrict__ p, float* out) {
    float c0 = cosf(p[0]), c1 = cosf(p[1]), c2 = cosf(p[2]), c3 = cosf(p[3]);
    out[0] = c1 * c2 * c3;
    out[1] = c0 * c1;
    out[2] = c0 * c1 * c2;
    out[3] = c0 * c1 * c2 * c3;
}

// Prefix kernel: grid 128 x 256. Each block computes h = relu(w2 @ cvec_f) into
// smem (w2 read is L2-broadcast, 8MB total), then each WARP owns one output
// element e and computes:
//   d_a[e]   = w_mix[e,:] . tile(cvec_attn)
//   d_b1f[e] = ln1_b[e] + w_out[e,:] . h
__global__ void __launch_bounds__(256) kFuse(const float* __restrict__ w_mix,
                                             const float* __restrict__ w_out,
                                             const float* __restrict__ w2,
                                             const float* __restrict__ attn_p,
                                             const float* __restrict__ ffn_p,
                                             const float* __restrict__ ln1_b) {
    const int t = threadIdx.x;
    const int warp = t >> 5, lane = t & 31;
    __shared__ __align__(16) float h[FFN_DIM];

    float cf[4], ca[4];
    circuit4(ffn_p, cf);
    circuit4(attn_p, ca);

    // h[k] = relu(w2[k,:] . cf), 16 per thread, coalesced
#pragma unroll
    for (int i = 0; i < 16; i++) {
        int k = t + i * 256;
        float4 w = reinterpret_cast<const float4*>(w2)[k];
        h[k] = fmaxf(w.x * cf[0] + w.y * cf[1] + w.z * cf[2] + w.w * cf[3], 0.0f);
    }
    __syncthreads();

    const int e = blockIdx.x * 8 + warp;   // 128*8 = 1024 = EMBED

    // a[e]: w_mix row = 256 float4, 8 per lane; pattern repeats every 4 elems
    const float4* wm = reinterpret_cast<const float4*>(w_mix + (size_t)e * EMBED);
    float sa = 0.0f;
#pragma unroll
    for (int i = 0; i < 8; i++) {
        float4 w = wm[lane + 32 * i];
        sa += w.x * ca[0] + w.y * ca[1] + w.z * ca[2] + w.w * ca[3];
    }

    // f[e]: w_out row = 1024 float4, 32 per lane
    const float4* wo = reinterpret_cast<const float4*>(w_out + (size_t)e * FFN_DIM);
    const float4* h4 = reinterpret_cast<const float4*>(h);
    float sf = 0.0f;
#pragma unroll
    for (int i = 0; i < 32; i++) {
        float4 w = wo[lane + 32 * i];
        float4 hv = h4[lane + 32 * i];
        sf += w.x * hv.x + w.y * hv.y + w.z * hv.z + w.w * hv.w;
    }

#pragma unroll
    for (int o = 16; o > 0; o >>= 1) {
        sa += __shfl_xor_sync(0xffffffffu, sa, o);
        sf += __shfl_xor_sync(0xffffffffu, sf, o);
    }
    if (lane == 0) {
        d_a[e] = sa;
        d_b1f[e] = ln1_b[e] + sf;
    }
}

// Main kernel: constants staged in smem once per block; warp-per-row with
// shfl-only reductions; each warp strides over multiple rows.
// out = g2*(z - m2)*r2 + b2,  z = g1*(x + a - m1)*r1 + b1f
__global__ void __launch_bounds__(256) kMain(const float4* __restrict__ x,
                                             const float4* __restrict__ g1,
                                             const float4* __restrict__ g2,
                                             const float4* __restrict__ b2,
                                             float4* __restrict__ out,
                                             int n_rows) {
    const int t = threadIdx.x;
    const int warp = t >> 5, lane = t & 31;

    // smem constant cache: [0:256) a, [256:512) g1, [512:768) b1f,
    //                      [768:1024) g2, [1024:1280) b2   (float4 units)
    __shared__ __align__(16) float4 cst[1280];
    cst[t]        = reinterpret_cast<const float4*>(d_a)[t];
    cst[t + 256]  = g1[t];
    cst[t + 512]  = reinterpret_cast<const float4*>(d_b1f)[t];
    cst[t + 768]  = g2[t];
    cst[t + 1024] = b2[t];
    __syncthreads();

    const int stride = gridDim.x * 8;
    for (int row = blockIdx.x * 8 + warp; row < n_rows; row += stride) {
        const float4* __restrict__ xr = x + (size_t)row * VEC4;

        // tv = x + a  (front-batched loads, MLP=8)
        float4 tv[8];
#pragma unroll
        for (int i = 0; i < 8; i++) {
            float4 xv = __ldcs(&xr[lane + 32 * i]);
            float4 av = cst[lane + 32 * i];
            tv[i].x = xv.x + av.x; tv[i].y = xv.y + av.y;
            tv[i].z = xv.z + av.z; tv[i].w = xv.w + av.w;
        }

        // Reduction 1
        float s = 0.0f, q = 0.0f;
#pragma unroll
        for (int i = 0; i < 8; i++) {
            s += tv[i].x + tv[i].y + tv[i].z + tv[i].w;
            q += tv[i].x * tv[i].x + tv[i].y * tv[i].y
               + tv[i].z * tv[i].z + tv[i].w * tv[i].w;
        }
#pragma unroll
        for (int o = 16; o > 0; o >>= 1) {
            s += __shfl_xor_sync(0xffffffffu, s, o);
            q += __shfl_xor_sync(0xffffffffu, q, o);
        }
        float m1 = s * (1.0f / EMBED);
        float r1 = rsqrtf(q * (1.0f / EMBED) - m1 * m1 + EPS);

        // z = g1*(tv-m1)*r1 + b1f, accumulate reduction 2
        s = 0.0f; q = 0.0f;
#pragma unroll
        for (int i = 0; i < 8; i++) {
            float4 gv = cst[lane + 32 * i + 256];
            float4 bv = cst[lane + 32 * i + 512];
            tv[i].x = gv.x * (tv[i].x - m1) * r1 + bv.x;
            tv[i].y = gv.y * (tv[i].y - m1) * r1 + bv.y;
            tv[i].z = gv.z * (tv[i].z - m1) * r1 + bv.z;
            tv[i].w = gv.w * (tv[i].w - m1) * r1 + bv.w;
            s += tv[i].x + tv[i].y + tv[i].z + tv[i].w;
            q += tv[i].x * tv[i].x + tv[i].y * tv[i].y
               + tv[i].z * tv[i].z + tv[i].w * tv[i].w;
        }
#pragma unroll
        for (int o = 16; o > 0; o >>= 1) {
            s += __shfl_xor_sync(0xffffffffu, s, o);
            q += __shfl_xor_sync(0xffffffffu, q, o);
        }
        float m2 = s * (1.0f / EMBED);
        float r2 = rsqrtf(q * (1.0f / EMBED) - m2 * m2 + EPS);

        float4* __restrict__ orow = out + (size_t)row * VEC4;
#pragma unroll
        for (int i = 0; i < 8; i++) {
            float4 gv = cst[lane + 32 * i + 768];
            float4 bv = cst[lane + 32 * i + 1024];
            float4 o;
            o.x = gv.x * (tv[i].x - m2) * r2 + bv.x;
            o.y = gv.y * (tv[i].y - m2) * r2 + bv.y;
            o.z = gv.z * (tv[i].z - m2) * r2 + bv.z;
            o.w = gv.w * (tv[i].w - m2) * r2 + bv.w;
            __stcs(&orow[lane + 32 * i], o);
        }
    }
}

extern "C" void kernel_launch(void* const* d_in, const int* in_sizes, int n_in,
                              void* d_out, int out_size) {
    // metadata order: x, wq, wk, wv, w_mix, attn_params, w1, w2, w_out,
    //                 ffn_params, ln1_g, ln1_b, ln2_g, ln2_b
    const float* x      = (const float*)d_in[0];
    const float* w_mix  = (const float*)d_in[4];
    const float* attn_p = (const float*)d_in[5];
    const float* w2     = (const float*)d_in[7];
    const float* w_out  = (const float*)d_in[8];
    const float* ffn_p  = (const float*)d_in[9];
    const float* ln1_g  = (const float*)d_in[10];
    const float* ln1_b  = (const float*)d_in[11];
    const float* ln2_g  = (const float*)d_in[12];
    const float* ln2_b  = (const float*)d_in[13];

    const int n_rows = in_sizes[0] / EMBED;  // B*S = 16384

    kFuse<<<EMBED / 8, 256>>>(w_mix, w_out, w2, attn_p, ffn_p, ln1_b);
    kMain<<<512, 256>>>(
        (const float4*)x,
        (const float4*)ln1_g,
        (const float4*)ln2_g, (const float4*)ln2_b,
        (float4*)d_out, n_rows);
}